// round 16
// baseline (speedup 1.0000x reference)
#include <cuda_runtime.h>
#include <cuda_bf16.h>
#include <cuda_fp16.h>
#include <math.h>

constexpr int B_  = 2;
constexpr int N_  = 4096;
constexpr int C_  = 256;
constexpr int H_  = 4;
constexpr int DH_ = 64;
constexpr int BN_ = B_ * N_;   // 8192
constexpr int BH_ = B_ * H_;   // 8

constexpr float QSCALE = 0.18033688011112042f;  // log2(e)/8
constexpr float VSCALE = 4096.0f;               // keep V*linv in f16 normal range
constexpr float OSCALE = 1.0f / 4096.0f;

// Scratch (device globals) — 16B-aligned
__device__ __align__(16) unsigned g_hb[BN_ * (C_ / 2)];        // bf16x2 LN output
__device__ __align__(16) unsigned g_wb[3 * C_ * (C_ / 2)];     // bf16x2 W, [z][n][k/2]
__device__ __align__(16) unsigned g_qb[BH_ * N_ * (DH_ / 2)];  // bf16x2, q*log2e/8
__device__ __align__(16) unsigned g_kb[BH_ * N_ * (DH_ / 2)];  // bf16x2
__device__ __align__(16) float    g_v[BH_ * N_ * DH_];
__device__ __align__(16) __half   g_vh[BH_ * DH_ * N_];        // V'' = V*linv*4096, [bh][d][j]
__device__ __align__(16) float    g_o[BN_ * C_];

// ---------------------------------------------------------------------------
// helpers
// ---------------------------------------------------------------------------
__device__ __forceinline__ float tf32r(float f) {
    unsigned u;
    asm("cvt.rna.tf32.f32 %0, %1;" : "=r"(u) : "f"(f));
    return __uint_as_float(u);
}

__device__ __forceinline__ void mma_tf32(float* c, const unsigned* a, const unsigned* b) {
    asm volatile(
        "mma.sync.aligned.m16n8k8.row.col.f32.tf32.tf32.f32 "
        "{%0,%1,%2,%3}, {%4,%5,%6,%7}, {%8,%9}, {%0,%1,%2,%3};\n"
        : "+f"(c[0]), "+f"(c[1]), "+f"(c[2]), "+f"(c[3])
        : "r"(a[0]), "r"(a[1]), "r"(a[2]), "r"(a[3]), "r"(b[0]), "r"(b[1]));
}

__device__ __forceinline__ void mma_bf16(float* c, const unsigned* a, const unsigned* b) {
    asm volatile(
        "mma.sync.aligned.m16n8k16.row.col.f32.bf16.bf16.f32 "
        "{%0,%1,%2,%3}, {%4,%5,%6,%7}, {%8,%9}, {%0,%1,%2,%3};\n"
        : "+f"(c[0]), "+f"(c[1]), "+f"(c[2]), "+f"(c[3])
        : "r"(a[0]), "r"(a[1]), "r"(a[2]), "r"(a[3]), "r"(b[0]), "r"(b[1]));
}

__device__ __forceinline__ void mma_f16(float* c, const unsigned* a, const unsigned* b) {
    asm volatile(
        "mma.sync.aligned.m16n8k16.row.col.f32.f16.f16.f32 "
        "{%0,%1,%2,%3}, {%4,%5,%6,%7}, {%8,%9}, {%0,%1,%2,%3};\n"
        : "+f"(c[0]), "+f"(c[1]), "+f"(c[2]), "+f"(c[3])
        : "r"(a[0]), "r"(a[1]), "r"(a[2]), "r"(a[3]), "r"(b[0]), "r"(b[1]));
}

__device__ __forceinline__ unsigned pack_bf16(float hi, float lo) {
    unsigned u;
    asm("cvt.rn.bf16x2.f32 %0, %1, %2;" : "=r"(u) : "f"(hi), "f"(lo));
    return u;
}

__device__ __forceinline__ unsigned cvt_f16x2(float hi, float lo) {
    unsigned u;
    asm("cvt.rn.f16x2.f32 %0, %1, %2;" : "=r"(u) : "f"(hi), "f"(lo));
    return u;
}

__device__ __forceinline__ unsigned ex2_f16x2(unsigned x) {
    unsigned y;
    asm("ex2.approx.f16x2 %0, %1;" : "=r"(y) : "r"(x));
    return y;
}

__device__ __forceinline__ unsigned hadd2(unsigned a, unsigned b) {
    unsigned y;
    asm("add.rn.f16x2 %0, %1, %2;" : "=r"(y) : "r"(a), "r"(b));
    return y;
}

__device__ __forceinline__ unsigned smem_u32(const void* p) {
    return (unsigned)__cvta_generic_to_shared(p);
}

__device__ __forceinline__ void ldsm_x4(unsigned& r0, unsigned& r1, unsigned& r2, unsigned& r3,
                                        unsigned addr) {
    asm volatile("ldmatrix.sync.aligned.m8n8.x4.shared.b16 {%0,%1,%2,%3}, [%4];"
                 : "=r"(r0), "=r"(r1), "=r"(r2), "=r"(r3) : "r"(addr));
}

__device__ __forceinline__ void cp16(unsigned dst_smem, const void* src) {
    asm volatile("cp.async.ca.shared.global [%0], [%1], 16;" :: "r"(dst_smem), "l"(src));
}
__device__ __forceinline__ void cp_commit() { asm volatile("cp.async.commit_group;"); }
template <int N>
__device__ __forceinline__ void cp_wait() { asm volatile("cp.async.wait_group %0;" :: "n"(N)); }

// ---------------------------------------------------------------------------
// 1) Fused LN + wprep.
// ---------------------------------------------------------------------------
constexpr int LN_BLOCKS = BN_ / 8;   // 1024

__global__ void __launch_bounds__(256) prep_kernel(
        const float* __restrict__ x, const float* __restrict__ pos,
        const float* __restrict__ gamma, const float* __restrict__ beta,
        const float* __restrict__ Wq, const float* __restrict__ Wk,
        const float* __restrict__ Wv) {
    if (blockIdx.x < LN_BLOCKS) {
        int warp = threadIdx.x >> 5, lane = threadIdx.x & 31;
        int row  = blockIdx.x * 8 + warp;
        const float4* xr = (const float4*)(x   + (size_t)row * C_);
        const float4* pr = (const float4*)(pos + (size_t)row * C_);
        float4 a0 = xr[lane],      p0 = pr[lane];
        float4 a1 = xr[lane + 32], p1 = pr[lane + 32];
        float v[8] = { a0.x + p0.x, a0.y + p0.y, a0.z + p0.z, a0.w + p0.w,
                       a1.x + p1.x, a1.y + p1.y, a1.z + p1.z, a1.w + p1.w };
        float s = 0.f, sq = 0.f;
        #pragma unroll
        for (int i = 0; i < 8; i++) { s += v[i]; sq += v[i] * v[i]; }
        #pragma unroll
        for (int off = 16; off > 0; off >>= 1) {
            s  += __shfl_xor_sync(0xffffffffu, s,  off);
            sq += __shfl_xor_sync(0xffffffffu, sq, off);
        }
        float mu  = s * (1.0f / C_);
        float var = sq * (1.0f / C_) - mu * mu;
        float rs  = rsqrtf(var + 1e-6f);
        float h[8];
        #pragma unroll
        for (int i = 0; i < 4; i++) {
            int c0 = lane * 4 + i, c1 = 128 + lane * 4 + i;
            h[i]     = (v[i]     - mu) * rs * gamma[c0] + beta[c0];
            h[i + 4] = (v[i + 4] - mu) * rs * gamma[c1] + beta[c1];
        }
        unsigned* o = g_hb + (size_t)row * 128;
        o[lane * 2]          = pack_bf16(h[1], h[0]);
        o[lane * 2 + 1]      = pack_bf16(h[3], h[2]);
        o[64 + lane * 2]     = pack_bf16(h[5], h[4]);
        o[64 + lane * 2 + 1] = pack_bf16(h[7], h[6]);
    } else {
        int wb = blockIdx.x - LN_BLOCKS;       // 0..95
        int z = wb / 32;
        const float* W = (z == 0) ? Wq : (z == 1) ? Wk : Wv;
        int n = threadIdx.x;
        int h = n >> 6, d = n & 63;
        int cp0 = (wb % 32) * 4;
        #pragma unroll
        for (int it = 0; it < 4; it++) {
            int c = (cp0 + it) * 2;
            float w0 = W[((size_t)h * C_ + c) * DH_ + d];
            float w1 = W[((size_t)h * C_ + c + 1) * DH_ + d];
            g_wb[((size_t)z * C_ + n) * 128 + cp0 + it] = pack_bf16(w1, w0);
        }
    }
}

// ---------------------------------------------------------------------------
// 2) QKV projection: bf16 mma (ldmatrix + cp.async double buffer).
// ---------------------------------------------------------------------------
constexpr int QKV_STAGE_U32 = 128 * 36;

__global__ void __launch_bounds__(256) qkv_kernel(
        const float* __restrict__ bq, const float* __restrict__ bk,
        const float* __restrict__ bv) {
    extern __shared__ unsigned char dynsm[];
    unsigned* Ast = (unsigned*)dynsm;                 // 2 x [128][36]
    unsigned* Bst = Ast + 2 * QKV_STAGE_U32;          // 2 x [128][36]

    int z = blockIdx.z;
    const float* bias = (z == 0) ? bq : (z == 1) ? bk : bv;
    int m0 = blockIdx.y * 128, n0 = blockIdx.x * 128;
    int tid = threadIdx.x, warp = tid >> 5, lane = tid & 31;
    int gq = lane >> 2, t4 = lane & 3;
    int wr = warp * 16;

    int kr = tid >> 3, kc4 = tid & 7;

    auto issue = [&](int kc) {
        int st = kc & 1;
        unsigned adst = smem_u32(&Ast[st * QKV_STAGE_U32]);
        unsigned bdst = smem_u32(&Bst[st * QKV_STAGE_U32]);
        #pragma unroll
        for (int it = 0; it < 4; it++) {
            int r = kr + it * 32;
            cp16(adst + (r * 36 + kc4 * 4) * 4, &g_hb[(size_t)(m0 + r) * 128 + kc * 32 + kc4 * 4]);
            cp16(bdst + (r * 36 + kc4 * 4) * 4,
                 &g_wb[((size_t)z * C_ + n0 + r) * 128 + kc * 32 + kc4 * 4]);
        }
        cp_commit();
    };

    unsigned baseA0 = smem_u32(&Ast[(wr + (lane & 15)) * 36 + ((lane >> 4) << 2)]);
    int brow = ((lane >> 4) << 3) + (lane & 7);
    unsigned baseB0 = smem_u32(&Bst[brow * 36 + (((lane >> 3) & 1) << 2)]);

    issue(0);

    float sacc[16][4] = {};
    for (int kc = 0; kc < 4; kc++) {
        if (kc < 3) issue(kc + 1);
        if (kc < 3) cp_wait<1>(); else cp_wait<0>();
        __syncthreads();
        unsigned baseA = baseA0 + (kc & 1) * QKV_STAGE_U32 * 4;
        unsigned baseB = baseB0 + (kc & 1) * QKV_STAGE_U32 * 4;
        #pragma unroll
        for (int ks = 0; ks < 4; ks++) {
            unsigned a[4];
            ldsm_x4(a[0], a[1], a[2], a[3], baseA + ks * 32);
            #pragma unroll
            for (int p = 0; p < 8; p++) {
                unsigned b[4];
                ldsm_x4(b[0], b[1], b[2], b[3], baseB + p * (16 * 36 * 4) + ks * 32);
                mma_bf16(sacc[2 * p],     a, &b[0]);
                mma_bf16(sacc[2 * p + 1], a, &b[2]);
            }
        }
        __syncthreads();
    }

    #pragma unroll
    for (int nf = 0; nf < 16; nf++) {
        int n = n0 + nf * 8 + t4 * 2;
        int h = n >> 6, d = n & 63;
        float b0 = bias[h * DH_ + d], b1 = bias[h * DH_ + d + 1];
        #pragma unroll
        for (int half = 0; half < 2; half++) {
            int rr = m0 + wr + gq + half * 8;
            int bb = rr >> 12, nn = rr & 4095;
            float v0 = sacc[nf][half * 2 + 0] + b0;
            float v1 = sacc[nf][half * 2 + 1] + b1;
            size_t bhrow = ((size_t)bb * H_ + h) * N_ + nn;
            if (z == 0)
                g_qb[bhrow * 32 + (d >> 1)] = pack_bf16(v1 * QSCALE, v0 * QSCALE);
            else if (z == 1)
                g_kb[bhrow * 32 + (d >> 1)] = pack_bf16(v1, v0);
            else {
                g_v[bhrow * DH_ + d]     = v0;
                g_v[bhrow * DH_ + d + 1] = v1;
            }
        }
    }
}

// ---------------------------------------------------------------------------
// 3) sumexp+vprep: one block owns a full (bh, j-tile). K resident (register
//    fragments), Q streamed over 32 chunks (2-stage). Ends with in-block
//    linv + V->f16 transpose. No cross-block coordination.
// ---------------------------------------------------------------------------
constexpr int SE_STAGE_U32 = 128 * 36;

__global__ void __launch_bounds__(256) sumexp_kernel() {
    extern __shared__ unsigned char dynsm[];
    unsigned* KsU = (unsigned*)dynsm;                 // [128][36] resident
    unsigned* Qst = KsU + SE_STAGE_U32;               // 2 x [128][36]
    __shared__ float redsm[8][32];
    __shared__ float linv_sh[128];

    int bh = blockIdx.y, j0 = blockIdx.x * 128;
    const unsigned* Qb = g_qb + (size_t)bh * N_ * 32;
    const unsigned* Kb = g_kb + (size_t)bh * N_ * 32;
    int tid = threadIdx.x, warp = tid >> 5, lane = tid & 31;
    int wj = (warp & 3) * 32;
    int wi = (warp >> 2) * 64;

    int kr = tid >> 3, kc4 = tid & 7;

    #pragma unroll
    for (int it = 0; it < 4; it++) {
        int r = kr + it * 32;
        cp16(smem_u32(&KsU[r * 36 + kc4 * 4]), &Kb[(size_t)(j0 + r) * 32 + kc4 * 4]);
        cp16(smem_u32(&Qst[r * 36 + kc4 * 4]), &Qb[(size_t)r * 32 + kc4 * 4]);
    }
    cp_commit();

    auto issueQ = [&](int c) {
        int st = c & 1;
        unsigned qdst = smem_u32(&Qst[st * SE_STAGE_U32]);
        #pragma unroll
        for (int it = 0; it < 4; it++) {
            int r = kr + it * 32;
            cp16(qdst + (r * 36 + kc4 * 4) * 4, &Qb[(size_t)(c * 128 + r) * 32 + kc4 * 4]);
        }
        cp_commit();
    };

    unsigned baseA0 = smem_u32(&Qst[(wi + (lane & 15)) * 36 + ((lane >> 4) << 2)]);
    int brow = ((lane >> 4) << 3) + (lane & 7);
    unsigned baseB = smem_u32(&KsU[(wj + brow) * 36 + (((lane >> 3) & 1) << 2)]);

    cp_wait<0>();
    __syncthreads();
    unsigned kres[4][4][2];
    #pragma unroll
    for (int p = 0; p < 2; p++)
        #pragma unroll
        for (int ks = 0; ks < 4; ks++) {
            unsigned b4[4];
            ldsm_x4(b4[0], b4[1], b4[2], b4[3], baseB + p * (16 * 36 * 4) + ks * 32);
            kres[ks][2 * p][0]     = b4[0];
            kres[ks][2 * p][1]     = b4[1];
            kres[ks][2 * p + 1][0] = b4[2];
            kres[ks][2 * p + 1][1] = b4[3];
        }

    float csum[4][2] = {};
    for (int c = 0; c < 32; c++) {
        if (c < 31) issueQ(c + 1);
        if (c < 31) cp_wait<1>(); else cp_wait<0>();
        __syncthreads();
        unsigned baseA = baseA0 + (c & 1) * SE_STAGE_U32 * 4;

        #pragma unroll
        for (int m = 0; m < 4; m++) {
            float sm[4][4] = {};
            #pragma unroll
            for (int ks = 0; ks < 4; ks++) {
                unsigned a[4];
                ldsm_x4(a[0], a[1], a[2], a[3], baseA + m * (16 * 36 * 4) + ks * 32);
                #pragma unroll
                for (int nf = 0; nf < 4; nf++)
                    mma_bf16(sm[nf], a, kres[ks][nf]);
            }
            #pragma unroll
            for (int nf = 0; nf < 4; nf++) {
                unsigned e0 = ex2_f16x2(cvt_f16x2(sm[nf][1], sm[nf][0]));
                unsigned e1 = ex2_f16x2(cvt_f16x2(sm[nf][3], sm[nf][2]));
                unsigned hs = hadd2(e0, e1);
                __half2 hh = *reinterpret_cast<__half2*>(&hs);
                float2 f = __half22float2(hh);
                csum[nf][0] += f.x;
                csum[nf][1] += f.y;
            }
        }
        __syncthreads();
    }

    #pragma unroll
    for (int nf = 0; nf < 4; nf++) {
        float px = csum[nf][0], py = csum[nf][1];
        #pragma unroll
        for (int off = 4; off < 32; off <<= 1) {
            px += __shfl_xor_sync(0xffffffffu, px, off);
            py += __shfl_xor_sync(0xffffffffu, py, off);
        }
        if (lane < 4) {
            redsm[warp][nf * 8 + lane * 2]     = px;
            redsm[warp][nf * 8 + lane * 2 + 1] = py;
        }
    }
    __syncthreads();
    if (tid < 128) {
        int g = tid >> 5, cc = tid & 31;
        float s = redsm[g][cc] + redsm[g + 4][cc];
        linv_sh[tid] = VSCALE / s;
    }
    __syncthreads();

    // fused vprep: g_vh[bh][d][j0..j0+127] = f16(V*linv*4096), via Qst overlay
    __half* Tb = (__half*)Qst;     // [64 d][136]
    const float* V = g_v + (size_t)bh * N_ * DH_;
    #pragma unroll
    for (int it = 0; it < 8; it++) {
        int idx = it * 256 + tid;
        int j = idx >> 4, q4 = idx & 15;
        float li = linv_sh[j];
        float4 v = *(const float4*)&V[(size_t)(j0 + j) * DH_ + q4 * 4];
        Tb[(q4 * 4 + 0) * 136 + j] = __float2half(v.x * li);
        Tb[(q4 * 4 + 1) * 136 + j] = __float2half(v.y * li);
        Tb[(q4 * 4 + 2) * 136 + j] = __float2half(v.z * li);
        Tb[(q4 * 4 + 3) * 136 + j] = __float2half(v.w * li);
    }
    __syncthreads();
    #pragma unroll
    for (int it = 0; it < 4; it++) {
        int idx = it * 256 + tid;
        int d = idx >> 4, u = idx & 15;
        *(uint4*)&g_vh[((size_t)bh * DH_ + d) * N_ + j0 + u * 8] = *(uint4*)&Tb[d * 136 + u * 8];
    }
}

// ---------------------------------------------------------------------------
// 5) av: 128 rows / 256 threads / 8 warps. 3-stage cp.async K/V pipeline.
//    Q A-fragments loaded directly from global (no Q smem tile).
// ---------------------------------------------------------------------------
constexpr int KSTAGE_U32 = 128 * 36;
constexpr int VSTAGE_HF  = 64 * 136;
constexpr int KSTAGE_B   = KSTAGE_U32 * 4;
constexpr int VSTAGE_B   = VSTAGE_HF * 2;

__global__ void __launch_bounds__(256, 2) av_kernel() {
    extern __shared__ unsigned char dynsm[];
    unsigned* Kst = (unsigned*)dynsm;                        // 3 x [128][36]
    __half* Vst = (__half*)(Kst + 3 * KSTAGE_U32);           // 3 x [64][136]

    int bh = blockIdx.y, i0 = blockIdx.x * 128;
    const unsigned* Qb = g_qb + (size_t)bh * N_ * 32;
    const unsigned* Kb = g_kb + (size_t)bh * N_ * 32;
    const __half* Vp = g_vh + (size_t)bh * DH_ * N_;
    int tid = threadIdx.x, warp = tid >> 5, lane = tid & 31;
    int gq = lane >> 2, t4 = lane & 3;
    int wr = warp * 16;

    int kr = tid >> 3, kc4 = tid & 7;
    int vd = tid >> 4, vq = tid & 15;

    auto issue = [&](int c) {
        int j0 = c * 128, st = c % 3;
        unsigned kdst = smem_u32(&Kst[st * KSTAGE_U32]);
        unsigned vdst = smem_u32(&Vst[st * VSTAGE_HF]);
        #pragma unroll
        for (int it = 0; it < 4; it++) {
            int r = kr + it * 32;
            cp16(kdst + (r * 36 + kc4 * 4) * 4, &Kb[(size_t)(j0 + r) * 32 + kc4 * 4]);
        }
        #pragma unroll
        for (int it = 0; it < 4; it++) {
            int d = vd + it * 16;
            cp16(vdst + (d * 136 + vq * 8) * 2, &Vp[(size_t)d * N_ + j0 + vq * 8]);
        }
        cp_commit();
    };

    int brow = ((lane >> 4) << 3) + (lane & 7);
    unsigned baseB0 = smem_u32(&Kst[brow * 36 + (((lane >> 3) & 1) << 2)]);
    unsigned baseV0 = smem_u32(&Vst[brow * 136 + (((lane >> 3) & 1) << 3)]);

    issue(0);
    issue(1);

    // Q A-fragments straight from global (same layout ldmatrix would deliver)
    unsigned aq[4][4];
    {
        const unsigned* q0 = &Qb[(size_t)(i0 + wr + gq) * 32];
        const unsigned* q1 = &Qb[(size_t)(i0 + wr + gq + 8) * 32];
        #pragma unroll
        for (int ks = 0; ks < 4; ks++) {
            aq[ks][0] = q0[ks * 8 + t4];
            aq[ks][1] = q1[ks * 8 + t4];
            aq[ks][2] = q0[ks * 8 + t4 + 4];
            aq[ks][3] = q1[ks * 8 + t4 + 4];
        }
    }

    float acc[8][4] = {};
    for (int c = 0; c < 32; c++) {
        if (c < 30)      { issue(c + 2); cp_wait<2>(); }
        else if (c == 30) cp_wait<1>();
        else              cp_wait<0>();
        __syncthreads();

        unsigned baseB = baseB0 + (c % 3) * KSTAGE_B;
        unsigned baseV = baseV0 + (c % 3) * VSTAGE_B;

        float sacc[16][4] = {};
        #pragma unroll
        for (int ks = 0; ks < 4; ks++) {
            #pragma unroll
            for (int p = 0; p < 8; p++) {
                unsigned b[4];
                ldsm_x4(b[0], b[1], b[2], b[3], baseB + p * (16 * 36 * 4) + ks * 32);
                mma_bf16(sacc[2 * p],     aq[ks], &b[0]);
                mma_bf16(sacc[2 * p + 1], aq[ks], &b[2]);
            }
        }

        #pragma unroll
        for (int k0 = 0; k0 < 128; k0 += 16) {
            int nf0 = k0 >> 3;
            unsigned a[4];
            a[0] = ex2_f16x2(cvt_f16x2(sacc[nf0][1],     sacc[nf0][0]));
            a[1] = ex2_f16x2(cvt_f16x2(sacc[nf0][3],     sacc[nf0][2]));
            a[2] = ex2_f16x2(cvt_f16x2(sacc[nf0 + 1][1], sacc[nf0 + 1][0]));
            a[3] = ex2_f16x2(cvt_f16x2(sacc[nf0 + 1][3], sacc[nf0 + 1][2]));
            #pragma unroll
            for (int p = 0; p < 4; p++) {
                unsigned b[4];
                ldsm_x4(b[0], b[1], b[2], b[3], baseV + p * (16 * 136 * 2) + k0 * 2);
                mma_f16(acc[2 * p],     a, &b[0]);
                mma_f16(acc[2 * p + 1], a, &b[2]);
            }
        }
        __syncthreads();
    }

    int b = bh >> 2, h = bh & 3;
    #pragma unroll
    for (int nd = 0; nd < 8; nd++) {
        int d = h * DH_ + nd * 8 + t4 * 2;
        int r0 = i0 + wr + gq, r1 = r0 + 8;
        g_o[((size_t)b * N_ + r0) * C_ + d]     = acc[nd][0] * OSCALE;
        g_o[((size_t)b * N_ + r0) * C_ + d + 1] = acc[nd][1] * OSCALE;
        g_o[((size_t)b * N_ + r1) * C_ + d]     = acc[nd][2] * OSCALE;
        g_o[((size_t)b * N_ + r1) * C_ + d + 1] = acc[nd][3] * OSCALE;
    }
}

// ---------------------------------------------------------------------------
// 6) oproj: out = g_o @ Wo + bo. tf32 mma, cp.async double-buffered.
// ---------------------------------------------------------------------------
constexpr int OP_A_U32 = 128 * 36;   // per stage
constexpr int OP_B_U32 = 32 * 132;   // per stage

__global__ void __launch_bounds__(256) oproj_kernel(const float* __restrict__ Wo,
                                                    const float* __restrict__ bo,
                                                    float* __restrict__ out) {
    extern __shared__ unsigned char dynsm[];
    float* Ast = (float*)dynsm;                 // 2 x [128][36]
    float* Bst = Ast + 2 * OP_A_U32;            // 2 x [32][132]

    int m0 = blockIdx.y * 128, n0 = blockIdx.x * 128;
    int tid = threadIdx.x, warp = tid >> 5, lane = tid & 31;
    int wm = warp >> 1, wn = warp & 1, gq = lane >> 2, t4 = lane & 3;

    int ar = tid >> 3, ac4 = tid & 7;
    int bk = tid >> 5, bn4 = tid & 31;

    auto issue = [&](int kc) {
        int st = kc & 1;
        unsigned adst = smem_u32(&Ast[st * OP_A_U32]);
        unsigned bdst = smem_u32(&Bst[st * OP_B_U32]);
        #pragma unroll
        for (int it = 0; it < 4; it++) {
            int r = ar + it * 32;
            cp16(adst + (r * 36 + ac4 * 4) * 4, &g_o[(size_t)(m0 + r) * C_ + kc * 32 + ac4 * 4]);
        }
        #pragma unroll
        for (int it = 0; it < 4; it++) {
            int k = bk + it * 8;
            cp16(bdst + (k * 132 + bn4 * 4) * 4, &Wo[(size_t)(kc * 32 + k) * C_ + n0 + bn4 * 4]);
        }
        cp_commit();
    };

    issue(0);

    float acc[2][8][4] = {};
    for (int kc = 0; kc < 8; kc++) {
        if (kc < 7) issue(kc + 1);
        if (kc < 7) cp_wait<1>(); else cp_wait<0>();
        __syncthreads();
        const float* As = Ast + (kc & 1) * OP_A_U32;
        const float* Bs = Bst + (kc & 1) * OP_B_U32;
        #pragma unroll
        for (int k0 = 0; k0 < 32; k0 += 8) {
            unsigned a[2][4], b[8][2];
            #pragma unroll
            for (int mf = 0; mf < 2; mf++) {
                int r = wm * 32 + mf * 16 + gq;
                a[mf][0] = __float_as_uint(tf32r(As[r * 36 + k0 + t4]));
                a[mf][1] = __float_as_uint(tf32r(As[(r + 8) * 36 + k0 + t4]));
                a[mf][2] = __float_as_uint(tf32r(As[r * 36 + k0 + t4 + 4]));
                a[mf][3] = __float_as_uint(tf32r(As[(r + 8) * 36 + k0 + t4 + 4]));
            }
            #pragma unroll
            for (int nf = 0; nf < 8; nf++) {
                int n = wn * 64 + nf * 8 + gq;
                b[nf][0] = __float_as_uint(tf32r(Bs[(k0 + t4) * 132 + n]));
                b[nf][1] = __float_as_uint(tf32r(Bs[(k0 + t4 + 4) * 132 + n]));
            }
            #pragma unroll
            for (int mf = 0; mf < 2; mf++)
                #pragma unroll
                for (int nf = 0; nf < 8; nf++)
                    mma_tf32(acc[mf][nf], a[mf], b[nf]);
        }
        __syncthreads();
    }
    #pragma unroll
    for (int mf = 0; mf < 2; mf++)
        #pragma unroll
        for (int nf = 0; nf < 8; nf++) {
            int c = n0 + wn * 64 + nf * 8 + t4 * 2;
            #pragma unroll
            for (int half = 0; half < 2; half++) {
                int rr = m0 + wm * 32 + mf * 16 + gq + half * 8;
                out[(size_t)rr * C_ + c]     = acc[mf][nf][half * 2 + 0] + bo[c];
                out[(size_t)rr * C_ + c + 1] = acc[mf][nf][half * 2 + 1] + bo[c + 1];
            }
        }
}

// ---------------------------------------------------------------------------
extern "C" void kernel_launch(void* const* d_in, const int* in_sizes, int n_in,
                              void* d_out, int out_size) {
    const float* x   = (const float*)d_in[0];
    const float* pos = (const float*)d_in[1];
    const float* Wq  = (const float*)d_in[2];
    const float* bq  = (const float*)d_in[3];
    const float* Wk  = (const float*)d_in[4];
    const float* bk  = (const float*)d_in[5];
    const float* Wv  = (const float*)d_in[6];
    const float* bv  = (const float*)d_in[7];
    const float* Wo  = (const float*)d_in[8];
    const float* bo  = (const float*)d_in[9];
    const float* g   = (const float*)d_in[10];
    const float* b   = (const float*)d_in[11];
    float* out = (float*)d_out;

    const int QKV_SMEM    = 4 * QKV_STAGE_U32 * 4;                             // 73728
    const int SUMEXP_SMEM = 3 * SE_STAGE_U32 * 4;                              // 55296
    const int AV_SMEM     = 3 * KSTAGE_B + 3 * VSTAGE_B;                       // 107520
    const int OP_SMEM     = (2 * OP_A_U32 + 2 * OP_B_U32) * 4;                 // 70656
    cudaFuncSetAttribute(qkv_kernel,    cudaFuncAttributeMaxDynamicSharedMemorySize, QKV_SMEM);
    cudaFuncSetAttribute(sumexp_kernel, cudaFuncAttributeMaxDynamicSharedMemorySize, SUMEXP_SMEM);
    cudaFuncSetAttribute(av_kernel,     cudaFuncAttributeMaxDynamicSharedMemorySize, AV_SMEM);
    cudaFuncSetAttribute(oproj_kernel,  cudaFuncAttributeMaxDynamicSharedMemorySize, OP_SMEM);

    prep_kernel<<<LN_BLOCKS + 96, 256>>>(x, pos, g, b, Wq, Wk, Wv);
    qkv_kernel<<<dim3(2, 64, 3), 256, QKV_SMEM>>>(bq, bk, bv);
    sumexp_kernel<<<dim3(N_ / 128, BH_), 256, SUMEXP_SMEM>>>();
    av_kernel<<<dim3(N_ / 128, BH_), 256, AV_SMEM>>>();
    oproj_kernel<<<dim3(2, 64), 256, OP_SMEM>>>(Wo, bo, out);
}

// round 17
// speedup vs baseline: 1.0285x; 1.0285x over previous
#include <cuda_runtime.h>
#include <cuda_bf16.h>
#include <cuda_fp16.h>
#include <math.h>

constexpr int B_  = 2;
constexpr int N_  = 4096;
constexpr int C_  = 256;
constexpr int H_  = 4;
constexpr int DH_ = 64;
constexpr int BN_ = B_ * N_;   // 8192
constexpr int BH_ = B_ * H_;   // 8

constexpr float QSCALE = 0.18033688011112042f;  // log2(e)/8
constexpr float VSCALE = 4096.0f;               // keep V*linv in f16 normal range
constexpr float OSCALE = 1.0f / 4096.0f;

// Scratch (device globals) — 16B-aligned
__device__ __align__(16) unsigned g_hb[BN_ * (C_ / 2)];        // bf16x2 LN output
__device__ __align__(16) unsigned g_wb[3 * C_ * (C_ / 2)];     // bf16x2 W, [z][n][k/2]
__device__ __align__(16) unsigned g_qb[BH_ * N_ * (DH_ / 2)];  // bf16x2, q*log2e/8
__device__ __align__(16) unsigned g_kb[BH_ * N_ * (DH_ / 2)];  // bf16x2
__device__ __align__(16) float    g_v[BH_ * N_ * DH_];
__device__ __align__(16) __half   g_vh[BH_ * DH_ * N_];        // V'' = V*linv*4096, [bh][d][j]
__device__ __align__(16) float    g_o[BN_ * C_];

// ---------------------------------------------------------------------------
// helpers
// ---------------------------------------------------------------------------
__device__ __forceinline__ float tf32r(float f) {
    unsigned u;
    asm("cvt.rna.tf32.f32 %0, %1;" : "=r"(u) : "f"(f));
    return __uint_as_float(u);
}

__device__ __forceinline__ void mma_tf32(float* c, const unsigned* a, const unsigned* b) {
    asm volatile(
        "mma.sync.aligned.m16n8k8.row.col.f32.tf32.tf32.f32 "
        "{%0,%1,%2,%3}, {%4,%5,%6,%7}, {%8,%9}, {%0,%1,%2,%3};\n"
        : "+f"(c[0]), "+f"(c[1]), "+f"(c[2]), "+f"(c[3])
        : "r"(a[0]), "r"(a[1]), "r"(a[2]), "r"(a[3]), "r"(b[0]), "r"(b[1]));
}

__device__ __forceinline__ void mma_bf16(float* c, const unsigned* a, const unsigned* b) {
    asm volatile(
        "mma.sync.aligned.m16n8k16.row.col.f32.bf16.bf16.f32 "
        "{%0,%1,%2,%3}, {%4,%5,%6,%7}, {%8,%9}, {%0,%1,%2,%3};\n"
        : "+f"(c[0]), "+f"(c[1]), "+f"(c[2]), "+f"(c[3])
        : "r"(a[0]), "r"(a[1]), "r"(a[2]), "r"(a[3]), "r"(b[0]), "r"(b[1]));
}

__device__ __forceinline__ void mma_f16(float* c, const unsigned* a, const unsigned* b) {
    asm volatile(
        "mma.sync.aligned.m16n8k16.row.col.f32.f16.f16.f32 "
        "{%0,%1,%2,%3}, {%4,%5,%6,%7}, {%8,%9}, {%0,%1,%2,%3};\n"
        : "+f"(c[0]), "+f"(c[1]), "+f"(c[2]), "+f"(c[3])
        : "r"(a[0]), "r"(a[1]), "r"(a[2]), "r"(a[3]), "r"(b[0]), "r"(b[1]));
}

__device__ __forceinline__ unsigned pack_bf16(float hi, float lo) {
    unsigned u;
    asm("cvt.rn.bf16x2.f32 %0, %1, %2;" : "=r"(u) : "f"(hi), "f"(lo));
    return u;
}

__device__ __forceinline__ unsigned cvt_f16x2(float hi, float lo) {
    unsigned u;
    asm("cvt.rn.f16x2.f32 %0, %1, %2;" : "=r"(u) : "f"(hi), "f"(lo));
    return u;
}

__device__ __forceinline__ unsigned ex2_f16x2(unsigned x) {
    unsigned y;
    asm("ex2.approx.f16x2 %0, %1;" : "=r"(y) : "r"(x));
    return y;
}

__device__ __forceinline__ unsigned hadd2(unsigned a, unsigned b) {
    unsigned y;
    asm("add.rn.f16x2 %0, %1, %2;" : "=r"(y) : "r"(a), "r"(b));
    return y;
}

__device__ __forceinline__ unsigned smem_u32(const void* p) {
    return (unsigned)__cvta_generic_to_shared(p);
}

__device__ __forceinline__ void ldsm_x4(unsigned& r0, unsigned& r1, unsigned& r2, unsigned& r3,
                                        unsigned addr) {
    asm volatile("ldmatrix.sync.aligned.m8n8.x4.shared.b16 {%0,%1,%2,%3}, [%4];"
                 : "=r"(r0), "=r"(r1), "=r"(r2), "=r"(r3) : "r"(addr));
}

__device__ __forceinline__ void cp16(unsigned dst_smem, const void* src) {
    asm volatile("cp.async.ca.shared.global [%0], [%1], 16;" :: "r"(dst_smem), "l"(src));
}
__device__ __forceinline__ void cp_commit() { asm volatile("cp.async.commit_group;"); }
template <int N>
__device__ __forceinline__ void cp_wait() { asm volatile("cp.async.wait_group %0;" :: "n"(N)); }

// ---------------------------------------------------------------------------
// 1) Fused LN + wprep.
// ---------------------------------------------------------------------------
constexpr int LN_BLOCKS = BN_ / 8;   // 1024

__global__ void __launch_bounds__(256) prep_kernel(
        const float* __restrict__ x, const float* __restrict__ pos,
        const float* __restrict__ gamma, const float* __restrict__ beta,
        const float* __restrict__ Wq, const float* __restrict__ Wk,
        const float* __restrict__ Wv) {
    if (blockIdx.x < LN_BLOCKS) {
        int warp = threadIdx.x >> 5, lane = threadIdx.x & 31;
        int row  = blockIdx.x * 8 + warp;
        const float4* xr = (const float4*)(x   + (size_t)row * C_);
        const float4* pr = (const float4*)(pos + (size_t)row * C_);
        float4 a0 = xr[lane],      p0 = pr[lane];
        float4 a1 = xr[lane + 32], p1 = pr[lane + 32];
        float v[8] = { a0.x + p0.x, a0.y + p0.y, a0.z + p0.z, a0.w + p0.w,
                       a1.x + p1.x, a1.y + p1.y, a1.z + p1.z, a1.w + p1.w };
        float s = 0.f, sq = 0.f;
        #pragma unroll
        for (int i = 0; i < 8; i++) { s += v[i]; sq += v[i] * v[i]; }
        #pragma unroll
        for (int off = 16; off > 0; off >>= 1) {
            s  += __shfl_xor_sync(0xffffffffu, s,  off);
            sq += __shfl_xor_sync(0xffffffffu, sq, off);
        }
        float mu  = s * (1.0f / C_);
        float var = sq * (1.0f / C_) - mu * mu;
        float rs  = rsqrtf(var + 1e-6f);
        float h[8];
        #pragma unroll
        for (int i = 0; i < 4; i++) {
            int c0 = lane * 4 + i, c1 = 128 + lane * 4 + i;
            h[i]     = (v[i]     - mu) * rs * gamma[c0] + beta[c0];
            h[i + 4] = (v[i + 4] - mu) * rs * gamma[c1] + beta[c1];
        }
        unsigned* o = g_hb + (size_t)row * 128;
        o[lane * 2]          = pack_bf16(h[1], h[0]);
        o[lane * 2 + 1]      = pack_bf16(h[3], h[2]);
        o[64 + lane * 2]     = pack_bf16(h[5], h[4]);
        o[64 + lane * 2 + 1] = pack_bf16(h[7], h[6]);
    } else {
        int wb = blockIdx.x - LN_BLOCKS;       // 0..95
        int z = wb / 32;
        const float* W = (z == 0) ? Wq : (z == 1) ? Wk : Wv;
        int n = threadIdx.x;
        int h = n >> 6, d = n & 63;
        int cp0 = (wb % 32) * 4;
        #pragma unroll
        for (int it = 0; it < 4; it++) {
            int c = (cp0 + it) * 2;
            float w0 = W[((size_t)h * C_ + c) * DH_ + d];
            float w1 = W[((size_t)h * C_ + c + 1) * DH_ + d];
            g_wb[((size_t)z * C_ + n) * 128 + cp0 + it] = pack_bf16(w1, w0);
        }
    }
}

// ---------------------------------------------------------------------------
// 2) QKV projection: bf16 mma (ldmatrix + cp.async double buffer).
// ---------------------------------------------------------------------------
constexpr int QKV_STAGE_U32 = 128 * 36;

__global__ void __launch_bounds__(256) qkv_kernel(
        const float* __restrict__ bq, const float* __restrict__ bk,
        const float* __restrict__ bv) {
    extern __shared__ unsigned char dynsm[];
    unsigned* Ast = (unsigned*)dynsm;                 // 2 x [128][36]
    unsigned* Bst = Ast + 2 * QKV_STAGE_U32;          // 2 x [128][36]

    int z = blockIdx.z;
    const float* bias = (z == 0) ? bq : (z == 1) ? bk : bv;
    int m0 = blockIdx.y * 128, n0 = blockIdx.x * 128;
    int tid = threadIdx.x, warp = tid >> 5, lane = tid & 31;
    int gq = lane >> 2, t4 = lane & 3;
    int wr = warp * 16;

    int kr = tid >> 3, kc4 = tid & 7;

    auto issue = [&](int kc) {
        int st = kc & 1;
        unsigned adst = smem_u32(&Ast[st * QKV_STAGE_U32]);
        unsigned bdst = smem_u32(&Bst[st * QKV_STAGE_U32]);
        #pragma unroll
        for (int it = 0; it < 4; it++) {
            int r = kr + it * 32;
            cp16(adst + (r * 36 + kc4 * 4) * 4, &g_hb[(size_t)(m0 + r) * 128 + kc * 32 + kc4 * 4]);
            cp16(bdst + (r * 36 + kc4 * 4) * 4,
                 &g_wb[((size_t)z * C_ + n0 + r) * 128 + kc * 32 + kc4 * 4]);
        }
        cp_commit();
    };

    unsigned baseA0 = smem_u32(&Ast[(wr + (lane & 15)) * 36 + ((lane >> 4) << 2)]);
    int brow = ((lane >> 4) << 3) + (lane & 7);
    unsigned baseB0 = smem_u32(&Bst[brow * 36 + (((lane >> 3) & 1) << 2)]);

    issue(0);

    float sacc[16][4] = {};
    for (int kc = 0; kc < 4; kc++) {
        if (kc < 3) issue(kc + 1);
        if (kc < 3) cp_wait<1>(); else cp_wait<0>();
        __syncthreads();
        unsigned baseA = baseA0 + (kc & 1) * QKV_STAGE_U32 * 4;
        unsigned baseB = baseB0 + (kc & 1) * QKV_STAGE_U32 * 4;
        #pragma unroll
        for (int ks = 0; ks < 4; ks++) {
            unsigned a[4];
            ldsm_x4(a[0], a[1], a[2], a[3], baseA + ks * 32);
            #pragma unroll
            for (int p = 0; p < 8; p++) {
                unsigned b[4];
                ldsm_x4(b[0], b[1], b[2], b[3], baseB + p * (16 * 36 * 4) + ks * 32);
                mma_bf16(sacc[2 * p],     a, &b[0]);
                mma_bf16(sacc[2 * p + 1], a, &b[2]);
            }
        }
        __syncthreads();
    }

    #pragma unroll
    for (int nf = 0; nf < 16; nf++) {
        int n = n0 + nf * 8 + t4 * 2;
        int h = n >> 6, d = n & 63;
        float b0 = bias[h * DH_ + d], b1 = bias[h * DH_ + d + 1];
        #pragma unroll
        for (int half = 0; half < 2; half++) {
            int rr = m0 + wr + gq + half * 8;
            int bb = rr >> 12, nn = rr & 4095;
            float v0 = sacc[nf][half * 2 + 0] + b0;
            float v1 = sacc[nf][half * 2 + 1] + b1;
            size_t bhrow = ((size_t)bb * H_ + h) * N_ + nn;
            if (z == 0)
                g_qb[bhrow * 32 + (d >> 1)] = pack_bf16(v1 * QSCALE, v0 * QSCALE);
            else if (z == 1)
                g_kb[bhrow * 32 + (d >> 1)] = pack_bf16(v1, v0);
            else {
                g_v[bhrow * DH_ + d]     = v0;
                g_v[bhrow * DH_ + d + 1] = v1;
            }
        }
    }
}

// ---------------------------------------------------------------------------
// 3) sumexp+vprep: one block owns a full (bh, j-tile). K resident (register
//    fragments), Q streamed over 32 chunks (2-stage). Ends with in-block
//    linv + V->f16 transpose. No cross-block coordination. (R16 config)
// ---------------------------------------------------------------------------
constexpr int SE_STAGE_U32 = 128 * 36;

__global__ void __launch_bounds__(256) sumexp_kernel() {
    extern __shared__ unsigned char dynsm[];
    unsigned* KsU = (unsigned*)dynsm;                 // [128][36] resident
    unsigned* Qst = KsU + SE_STAGE_U32;               // 2 x [128][36]
    __shared__ float redsm[8][32];
    __shared__ float linv_sh[128];

    int bh = blockIdx.y, j0 = blockIdx.x * 128;
    const unsigned* Qb = g_qb + (size_t)bh * N_ * 32;
    const unsigned* Kb = g_kb + (size_t)bh * N_ * 32;
    int tid = threadIdx.x, warp = tid >> 5, lane = tid & 31;
    int wj = (warp & 3) * 32;
    int wi = (warp >> 2) * 64;

    int kr = tid >> 3, kc4 = tid & 7;

    #pragma unroll
    for (int it = 0; it < 4; it++) {
        int r = kr + it * 32;
        cp16(smem_u32(&KsU[r * 36 + kc4 * 4]), &Kb[(size_t)(j0 + r) * 32 + kc4 * 4]);
        cp16(smem_u32(&Qst[r * 36 + kc4 * 4]), &Qb[(size_t)r * 32 + kc4 * 4]);
    }
    cp_commit();

    auto issueQ = [&](int c) {
        int st = c & 1;
        unsigned qdst = smem_u32(&Qst[st * SE_STAGE_U32]);
        #pragma unroll
        for (int it = 0; it < 4; it++) {
            int r = kr + it * 32;
            cp16(qdst + (r * 36 + kc4 * 4) * 4, &Qb[(size_t)(c * 128 + r) * 32 + kc4 * 4]);
        }
        cp_commit();
    };

    unsigned baseA0 = smem_u32(&Qst[(wi + (lane & 15)) * 36 + ((lane >> 4) << 2)]);
    int brow = ((lane >> 4) << 3) + (lane & 7);
    unsigned baseB = smem_u32(&KsU[(wj + brow) * 36 + (((lane >> 3) & 1) << 2)]);

    cp_wait<0>();
    __syncthreads();
    unsigned kres[4][4][2];
    #pragma unroll
    for (int p = 0; p < 2; p++)
        #pragma unroll
        for (int ks = 0; ks < 4; ks++) {
            unsigned b4[4];
            ldsm_x4(b4[0], b4[1], b4[2], b4[3], baseB + p * (16 * 36 * 4) + ks * 32);
            kres[ks][2 * p][0]     = b4[0];
            kres[ks][2 * p][1]     = b4[1];
            kres[ks][2 * p + 1][0] = b4[2];
            kres[ks][2 * p + 1][1] = b4[3];
        }

    float csum[4][2] = {};
    for (int c = 0; c < 32; c++) {
        if (c < 31) issueQ(c + 1);
        if (c < 31) cp_wait<1>(); else cp_wait<0>();
        __syncthreads();
        unsigned baseA = baseA0 + (c & 1) * SE_STAGE_U32 * 4;

        #pragma unroll
        for (int m = 0; m < 4; m++) {
            float sm[4][4] = {};
            #pragma unroll
            for (int ks = 0; ks < 4; ks++) {
                unsigned a[4];
                ldsm_x4(a[0], a[1], a[2], a[3], baseA + m * (16 * 36 * 4) + ks * 32);
                #pragma unroll
                for (int nf = 0; nf < 4; nf++)
                    mma_bf16(sm[nf], a, kres[ks][nf]);
            }
            #pragma unroll
            for (int nf = 0; nf < 4; nf++) {
                unsigned e0 = ex2_f16x2(cvt_f16x2(sm[nf][1], sm[nf][0]));
                unsigned e1 = ex2_f16x2(cvt_f16x2(sm[nf][3], sm[nf][2]));
                unsigned hs = hadd2(e0, e1);
                __half2 hh = *reinterpret_cast<__half2*>(&hs);
                float2 f = __half22float2(hh);
                csum[nf][0] += f.x;
                csum[nf][1] += f.y;
            }
        }
        __syncthreads();
    }

    #pragma unroll
    for (int nf = 0; nf < 4; nf++) {
        float px = csum[nf][0], py = csum[nf][1];
        #pragma unroll
        for (int off = 4; off < 32; off <<= 1) {
            px += __shfl_xor_sync(0xffffffffu, px, off);
            py += __shfl_xor_sync(0xffffffffu, py, off);
        }
        if (lane < 4) {
            redsm[warp][nf * 8 + lane * 2]     = px;
            redsm[warp][nf * 8 + lane * 2 + 1] = py;
        }
    }
    __syncthreads();
    if (tid < 128) {
        int g = tid >> 5, cc = tid & 31;
        float s = redsm[g][cc] + redsm[g + 4][cc];
        linv_sh[tid] = VSCALE / s;
    }
    __syncthreads();

    // fused vprep: g_vh[bh][d][j0..j0+127] = f16(V*linv*4096), via Qst overlay
    __half* Tb = (__half*)Qst;     // [64 d][136]
    const float* V = g_v + (size_t)bh * N_ * DH_;
    #pragma unroll
    for (int it = 0; it < 8; it++) {
        int idx = it * 256 + tid;
        int j = idx >> 4, q4 = idx & 15;
        float li = linv_sh[j];
        float4 v = *(const float4*)&V[(size_t)(j0 + j) * DH_ + q4 * 4];
        Tb[(q4 * 4 + 0) * 136 + j] = __float2half(v.x * li);
        Tb[(q4 * 4 + 1) * 136 + j] = __float2half(v.y * li);
        Tb[(q4 * 4 + 2) * 136 + j] = __float2half(v.z * li);
        Tb[(q4 * 4 + 3) * 136 + j] = __float2half(v.w * li);
    }
    __syncthreads();
    #pragma unroll
    for (int it = 0; it < 4; it++) {
        int idx = it * 256 + tid;
        int d = idx >> 4, u = idx & 15;
        *(uint4*)&g_vh[((size_t)bh * DH_ + d) * N_ + j0 + u * 8] = *(uint4*)&Tb[d * 136 + u * 8];
    }
}

// ---------------------------------------------------------------------------
// 5) av: 128 rows / 256 threads / 8 warps, 2-stage cp.async pipeline.
//    Q smem tile + register-resident A-fragments (R14 config).
// ---------------------------------------------------------------------------
constexpr int KSTAGE_U32 = 128 * 36;
constexpr int VSTAGE_HF  = 64 * 136;
constexpr int KSTAGE_B   = KSTAGE_U32 * 4;
constexpr int VSTAGE_B   = VSTAGE_HF * 2;

__global__ void __launch_bounds__(256, 2) av_kernel() {
    extern __shared__ unsigned char dynsm[];
    unsigned* QsU = (unsigned*)dynsm;                        // [128][36]
    unsigned* Kst = QsU + 128 * 36;                          // 2 x [128][36]
    __half* Vst = (__half*)(Kst + 2 * KSTAGE_U32);           // 2 x [64][136]

    int bh = blockIdx.y, i0 = blockIdx.x * 128;
    const unsigned* Qb = g_qb + (size_t)bh * N_ * 32;
    const unsigned* Kb = g_kb + (size_t)bh * N_ * 32;
    const __half* Vp = g_vh + (size_t)bh * DH_ * N_;
    int tid = threadIdx.x, warp = tid >> 5, lane = tid & 31;
    int gq = lane >> 2, t4 = lane & 3;
    int wr = warp * 16;

    #pragma unroll
    for (int it = 0; it < 4; it++) {
        int idx = it * 256 + tid;
        int r = idx >> 3, c4 = idx & 7;
        *(uint4*)&QsU[r * 36 + c4 * 4] = *(const uint4*)&Qb[(size_t)(i0 + r) * 32 + c4 * 4];
    }

    int kr = tid >> 3, kc4 = tid & 7;
    int vd = tid >> 4, vq = tid & 15;

    auto issue = [&](int c) {
        int j0 = c * 128, st = c & 1;
        unsigned kdst = smem_u32(&Kst[st * KSTAGE_U32]);
        unsigned vdst = smem_u32(&Vst[st * VSTAGE_HF]);
        #pragma unroll
        for (int it = 0; it < 4; it++) {
            int r = kr + it * 32;
            cp16(kdst + (r * 36 + kc4 * 4) * 4, &Kb[(size_t)(j0 + r) * 32 + kc4 * 4]);
        }
        #pragma unroll
        for (int it = 0; it < 4; it++) {
            int d = vd + it * 16;
            cp16(vdst + (d * 136 + vq * 8) * 2, &Vp[(size_t)d * N_ + j0 + vq * 8]);
        }
        cp_commit();
    };

    unsigned baseA = smem_u32(&QsU[(wr + (lane & 15)) * 36 + ((lane >> 4) << 2)]);
    int brow = ((lane >> 4) << 3) + (lane & 7);
    unsigned baseB0 = smem_u32(&Kst[brow * 36 + (((lane >> 3) & 1) << 2)]);
    unsigned baseV0 = smem_u32(&Vst[brow * 136 + (((lane >> 3) & 1) << 3)]);

    issue(0);

    unsigned aq[4][4];      // register-resident Q fragments
    float acc[8][4] = {};
    for (int c = 0; c < 32; c++) {
        if (c < 31) issue(c + 1);
        if (c < 31) cp_wait<1>(); else cp_wait<0>();
        __syncthreads();

        if (c == 0) {
            #pragma unroll
            for (int ks = 0; ks < 4; ks++)
                ldsm_x4(aq[ks][0], aq[ks][1], aq[ks][2], aq[ks][3], baseA + ks * 32);
        }

        unsigned baseB = baseB0 + (c & 1) * KSTAGE_B;
        unsigned baseV = baseV0 + (c & 1) * VSTAGE_B;

        float sacc[16][4] = {};
        #pragma unroll
        for (int ks = 0; ks < 4; ks++) {
            #pragma unroll
            for (int p = 0; p < 8; p++) {
                unsigned b[4];
                ldsm_x4(b[0], b[1], b[2], b[3], baseB + p * (16 * 36 * 4) + ks * 32);
                mma_bf16(sacc[2 * p],     aq[ks], &b[0]);
                mma_bf16(sacc[2 * p + 1], aq[ks], &b[2]);
            }
        }

        #pragma unroll
        for (int k0 = 0; k0 < 128; k0 += 16) {
            int nf0 = k0 >> 3;
            unsigned a[4];
            a[0] = ex2_f16x2(cvt_f16x2(sacc[nf0][1],     sacc[nf0][0]));
            a[1] = ex2_f16x2(cvt_f16x2(sacc[nf0][3],     sacc[nf0][2]));
            a[2] = ex2_f16x2(cvt_f16x2(sacc[nf0 + 1][1], sacc[nf0 + 1][0]));
            a[3] = ex2_f16x2(cvt_f16x2(sacc[nf0 + 1][3], sacc[nf0 + 1][2]));
            #pragma unroll
            for (int p = 0; p < 4; p++) {
                unsigned b[4];
                ldsm_x4(b[0], b[1], b[2], b[3], baseV + p * (16 * 136 * 2) + k0 * 2);
                mma_f16(acc[2 * p],     a, &b[0]);
                mma_f16(acc[2 * p + 1], a, &b[2]);
            }
        }
        __syncthreads();
    }

    int b = bh >> 2, h = bh & 3;
    #pragma unroll
    for (int nd = 0; nd < 8; nd++) {
        int d = h * DH_ + nd * 8 + t4 * 2;
        int r0 = i0 + wr + gq, r1 = r0 + 8;
        g_o[((size_t)b * N_ + r0) * C_ + d]     = acc[nd][0] * OSCALE;
        g_o[((size_t)b * N_ + r0) * C_ + d + 1] = acc[nd][1] * OSCALE;
        g_o[((size_t)b * N_ + r1) * C_ + d]     = acc[nd][2] * OSCALE;
        g_o[((size_t)b * N_ + r1) * C_ + d + 1] = acc[nd][3] * OSCALE;
    }
}

// ---------------------------------------------------------------------------
// 6) oproj: out = g_o @ Wo + bo. tf32 mma, cp.async double-buffered.
// ---------------------------------------------------------------------------
constexpr int OP_A_U32 = 128 * 36;   // per stage
constexpr int OP_B_U32 = 32 * 132;   // per stage

__global__ void __launch_bounds__(256) oproj_kernel(const float* __restrict__ Wo,
                                                    const float* __restrict__ bo,
                                                    float* __restrict__ out) {
    extern __shared__ unsigned char dynsm[];
    float* Ast = (float*)dynsm;                 // 2 x [128][36]
    float* Bst = Ast + 2 * OP_A_U32;            // 2 x [32][132]

    int m0 = blockIdx.y * 128, n0 = blockIdx.x * 128;
    int tid = threadIdx.x, warp = tid >> 5, lane = tid & 31;
    int wm = warp >> 1, wn = warp & 1, gq = lane >> 2, t4 = lane & 3;

    int ar = tid >> 3, ac4 = tid & 7;
    int bk = tid >> 5, bn4 = tid & 31;

    auto issue = [&](int kc) {
        int st = kc & 1;
        unsigned adst = smem_u32(&Ast[st * OP_A_U32]);
        unsigned bdst = smem_u32(&Bst[st * OP_B_U32]);
        #pragma unroll
        for (int it = 0; it < 4; it++) {
            int r = ar + it * 32;
            cp16(adst + (r * 36 + ac4 * 4) * 4, &g_o[(size_t)(m0 + r) * C_ + kc * 32 + ac4 * 4]);
        }
        #pragma unroll
        for (int it = 0; it < 4; it++) {
            int k = bk + it * 8;
            cp16(bdst + (k * 132 + bn4 * 4) * 4, &Wo[(size_t)(kc * 32 + k) * C_ + n0 + bn4 * 4]);
        }
        cp_commit();
    };

    issue(0);

    float acc[2][8][4] = {};
    for (int kc = 0; kc < 8; kc++) {
        if (kc < 7) issue(kc + 1);
        if (kc < 7) cp_wait<1>(); else cp_wait<0>();
        __syncthreads();
        const float* As = Ast + (kc & 1) * OP_A_U32;
        const float* Bs = Bst + (kc & 1) * OP_B_U32;
        #pragma unroll
        for (int k0 = 0; k0 < 32; k0 += 8) {
            unsigned a[2][4], b[8][2];
            #pragma unroll
            for (int mf = 0; mf < 2; mf++) {
                int r = wm * 32 + mf * 16 + gq;
                a[mf][0] = __float_as_uint(tf32r(As[r * 36 + k0 + t4]));
                a[mf][1] = __float_as_uint(tf32r(As[(r + 8) * 36 + k0 + t4]));
                a[mf][2] = __float_as_uint(tf32r(As[r * 36 + k0 + t4 + 4]));
                a[mf][3] = __float_as_uint(tf32r(As[(r + 8) * 36 + k0 + t4 + 4]));
            }
            #pragma unroll
            for (int nf = 0; nf < 8; nf++) {
                int n = wn * 64 + nf * 8 + gq;
                b[nf][0] = __float_as_uint(tf32r(Bs[(k0 + t4) * 132 + n]));
                b[nf][1] = __float_as_uint(tf32r(Bs[(k0 + t4 + 4) * 132 + n]));
            }
            #pragma unroll
            for (int mf = 0; mf < 2; mf++)
                #pragma unroll
                for (int nf = 0; nf < 8; nf++)
                    mma_tf32(acc[mf][nf], a[mf], b[nf]);
        }
        __syncthreads();
    }
    #pragma unroll
    for (int mf = 0; mf < 2; mf++)
        #pragma unroll
        for (int nf = 0; nf < 8; nf++) {
            int c = n0 + wn * 64 + nf * 8 + t4 * 2;
            #pragma unroll
            for (int half = 0; half < 2; half++) {
                int rr = m0 + wm * 32 + mf * 16 + gq + half * 8;
                out[(size_t)rr * C_ + c]     = acc[mf][nf][half * 2 + 0] + bo[c];
                out[(size_t)rr * C_ + c + 1] = acc[mf][nf][half * 2 + 1] + bo[c + 1];
            }
        }
}

// ---------------------------------------------------------------------------
extern "C" void kernel_launch(void* const* d_in, const int* in_sizes, int n_in,
                              void* d_out, int out_size) {
    const float* x   = (const float*)d_in[0];
    const float* pos = (const float*)d_in[1];
    const float* Wq  = (const float*)d_in[2];
    const float* bq  = (const float*)d_in[3];
    const float* Wk  = (const float*)d_in[4];
    const float* bk  = (const float*)d_in[5];
    const float* Wv  = (const float*)d_in[6];
    const float* bv  = (const float*)d_in[7];
    const float* Wo  = (const float*)d_in[8];
    const float* bo  = (const float*)d_in[9];
    const float* g   = (const float*)d_in[10];
    const float* b   = (const float*)d_in[11];
    float* out = (float*)d_out;

    const int QKV_SMEM    = 4 * QKV_STAGE_U32 * 4;                             // 73728
    const int SUMEXP_SMEM = 3 * SE_STAGE_U32 * 4;                              // 55296
    const int AV_SMEM     = 128 * 36 * 4 + 2 * KSTAGE_B + 2 * VSTAGE_B;        // 90112
    const int OP_SMEM     = (2 * OP_A_U32 + 2 * OP_B_U32) * 4;                 // 70656
    cudaFuncSetAttribute(qkv_kernel,    cudaFuncAttributeMaxDynamicSharedMemorySize, QKV_SMEM);
    cudaFuncSetAttribute(sumexp_kernel, cudaFuncAttributeMaxDynamicSharedMemorySize, SUMEXP_SMEM);
    cudaFuncSetAttribute(av_kernel,     cudaFuncAttributeMaxDynamicSharedMemorySize, AV_SMEM);
    cudaFuncSetAttribute(oproj_kernel,  cudaFuncAttributeMaxDynamicSharedMemorySize, OP_SMEM);

    prep_kernel<<<LN_BLOCKS + 96, 256>>>(x, pos, g, b, Wq, Wk, Wv);
    qkv_kernel<<<dim3(2, 64, 3), 256, QKV_SMEM>>>(bq, bk, bv);
    sumexp_kernel<<<dim3(N_ / 128, BH_), 256, SUMEXP_SMEM>>>();
    av_kernel<<<dim3(N_ / 128, BH_), 256, AV_SMEM>>>();
    oproj_kernel<<<dim3(2, 64), 256, OP_SMEM>>>(Wo, bo, out);
}